// round 6
// baseline (speedup 1.0000x reference)
#include <cuda_runtime.h>
#include <cstdint>

#define MAX_SEGS 65536
#define MAX_NB   64

__device__ int g_starts[MAX_SEGS];     // block-local exclusive prefix (per 1024-chunk)
__device__ int g_blocktot[MAX_NB];     // per-chunk totals
__device__ int g_ready;                // scanners completed (reset each launch)
__device__ int g_done;                 // CTAs completed (reset each launch)

// ---------------------------------------------------------------------------
// Fused: scan (first nb CTAs) + spin-sync + segment mean. One launch.
// ---------------------------------------------------------------------------
__global__ __launch_bounds__(128)
void fused_seg_mean(const float* __restrict__ data,
                    const int* __restrict__ sz,
                    float* __restrict__ out,
                    int n_seg, int nb) {
    const int seg = blockIdx.x;
    const int t = threadIdx.x;
    const int w = t >> 5;
    const int l = t & 31;

    const int len = sz[seg];            // independent of scan: issue early

    // ---- Phase A: CTAs 0..nb-1 scan their 1024-element chunk ----
    if (seg < nb) {
        const int base_i = seg << 10;
        int vals[8];
        int local = 0;
        #pragma unroll
        for (int i = 0; i < 8; ++i) {
            const int idx = base_i + t * 8 + i;
            const int v = (idx < n_seg) ? sz[idx] : 0;
            vals[i] = v;
            local += v;
        }
        // warp inclusive scan of per-thread sums
        int inc = local;
        #pragma unroll
        for (int d = 1; d < 32; d <<= 1) {
            int u = __shfl_up_sync(0xFFFFFFFFu, inc, d);
            if (l >= d) inc += u;
        }
        __shared__ int s_wt[4], s_wo[4];
        if (l == 31) s_wt[w] = inc;
        __syncthreads();
        if (t == 0) {
            int run = 0;
            #pragma unroll
            for (int i = 0; i < 4; ++i) { s_wo[i] = run; run += s_wt[i]; }
            g_blocktot[seg] = run;      // chunk total
        }
        __syncthreads();
        int run = s_wo[w] + (inc - local);   // thread-exclusive offset
        #pragma unroll
        for (int i = 0; i < 8; ++i) {
            const int idx = base_i + t * 8 + i;
            if (idx < n_seg) g_starts[idx] = run;
            run += vals[i];
        }
        __threadfence();
        __syncthreads();
        if (t == 0) atomicAdd(&g_ready, 1);
    }

    // ---- Phase B: wait for all scanners, derive absolute start ----
    if (t == 0) {
        while (*(volatile int*)&g_ready < nb) { }
        __threadfence();                // acquire scanners' stores
    }
    __syncthreads();

    __shared__ int s_start;
    if (w == 0) {
        const int b = seg >> 10;
        const int v0 = (l < nb)      ? g_blocktot[l]      : 0;
        const int v1 = (l + 32 < nb) ? g_blocktot[l + 32] : 0;
        int s = ((l < b) ? v0 : 0) + ((l + 32 < b) ? v1 : 0);
        #pragma unroll
        for (int d = 16; d > 0; d >>= 1)
            s += __shfl_xor_sync(0xFFFFFFFFu, s, d);
        if (l == 0) s_start = s + g_starts[seg];
    }
    __syncthreads();
    const int start = s_start;

    // ---- Phase C: segment mean (unchanged hot loop) ----
    const float4* __restrict__ base =
        reinterpret_cast<const float4*>(data) + (size_t)start * 32 + l;

    float4 acc = make_float4(0.f, 0.f, 0.f, 0.f);

    if (len == 64) {
        #pragma unroll
        for (int b2 = 0; b2 < 2; ++b2) {
            float4 v[8];
            #pragma unroll
            for (int i = 0; i < 8; ++i)
                v[i] = __ldcs(&base[(size_t)(w + (b2 * 8 + i) * 4) * 32]);
            #pragma unroll
            for (int i = 0; i < 8; ++i) {
                acc.x += v[i].x; acc.y += v[i].y;
                acc.z += v[i].z; acc.w += v[i].w;
            }
        }
    } else {
        int r = w;
        for (; r + 12 < len; r += 16) {
            float4 v0 = __ldcs(&base[(size_t)(r     ) * 32]);
            float4 v1 = __ldcs(&base[(size_t)(r +  4) * 32]);
            float4 v2 = __ldcs(&base[(size_t)(r +  8) * 32]);
            float4 v3 = __ldcs(&base[(size_t)(r + 12) * 32]);
            acc.x += v0.x + v1.x + v2.x + v3.x;
            acc.y += v0.y + v1.y + v2.y + v3.y;
            acc.z += v0.z + v1.z + v2.z + v3.z;
            acc.w += v0.w + v1.w + v2.w + v3.w;
        }
        for (; r < len; r += 4) {
            float4 v = __ldcs(&base[(size_t)r * 32]);
            acc.x += v.x; acc.y += v.y; acc.z += v.z; acc.w += v.w;
        }
    }

    __shared__ float4 sm[4][32];
    sm[w][l] = acc;
    __syncthreads();

    if (w == 0) {
        float4 a = sm[0][l];
        float4 b = sm[1][l];
        float4 c = sm[2][l];
        float4 d = sm[3][l];
        const float inv = (len > 0) ? (1.0f / (float)len) : 0.0f;
        float4 o;
        o.x = (a.x + b.x + c.x + d.x) * inv;
        o.y = (a.y + b.y + c.y + d.y) * inv;
        o.z = (a.z + b.z + c.z + d.z) * inv;
        o.w = (a.w + b.w + c.w + d.w) * inv;
        __stcs(&reinterpret_cast<float4*>(out)[(size_t)seg * 32 + l], o);
    }

    // ---- Phase D: replay-safe reset (last CTA zeroes the flags) ----
    __threadfence();
    __syncthreads();
    if (t == 0) {
        const int d = atomicAdd(&g_done, 1);
        if (d == (int)gridDim.x - 1) {
            g_done = 0;
            *(volatile int*)&g_ready = 0;
            __threadfence();
        }
    }
}

// ---------------------------------------------------------------------------
// kernel_launch: single fused launch.
// ---------------------------------------------------------------------------
extern "C" void kernel_launch(void* const* d_in, const int* in_sizes, int n_in,
                              void* d_out, int out_size) {
    const float* data = (const float*)d_in[0];
    const int*   sz   = (const int*)d_in[1];
    float*       out  = (float*)d_out;
    const int n_seg = in_sizes[1];
    const int nb    = (n_seg + 1023) >> 10;

    fused_seg_mean<<<n_seg, 128>>>(data, sz, out, n_seg, nb);
}

// round 7
// speedup vs baseline: 1.1024x; 1.1024x over previous
#include <cuda_runtime.h>
#include <cstdint>

#define MAX_SEGS 65536
#define MAX_NB   64
#define SCAN_BLK 1024

__device__ int g_starts[MAX_SEGS];   // chunk-local exclusive prefix
__device__ int g_blocktot[MAX_NB];   // per-chunk totals

// ---------------------------------------------------------------------------
// K1: per-chunk exclusive scan. grid = ceil(n/1024), block = 1024.
// Coalesced 1 int/thread; warp shfl scan + warp-total scan.
// ---------------------------------------------------------------------------
__global__ void scan_local_kernel(const int* __restrict__ sz, int n) {
    __shared__ int s_tot[32];
    __shared__ int s_off[32];

    const int t    = threadIdx.x;
    const int lane = t & 31;
    const int wid  = t >> 5;
    const int gidx = blockIdx.x * SCAN_BLK + t;

    int v = (gidx < n) ? sz[gidx] : 0;

    int inc = v;
    #pragma unroll
    for (int d = 1; d < 32; d <<= 1) {
        int u = __shfl_up_sync(0xFFFFFFFFu, inc, d);
        if (lane >= d) inc += u;
    }
    if (lane == 31) s_tot[wid] = inc;
    __syncthreads();

    if (wid == 0) {
        int wv = s_tot[lane];
        int winc = wv;
        #pragma unroll
        for (int d = 1; d < 32; d <<= 1) {
            int u = __shfl_up_sync(0xFFFFFFFFu, winc, d);
            if (lane >= d) winc += u;
        }
        s_off[lane] = winc - wv;
        if (lane == 31) g_blocktot[blockIdx.x] = winc;
    }
    __syncthreads();

    if (gidx < n) g_starts[gidx] = s_off[wid] + (inc - v);

    // release PDL dependents
    asm volatile("griddepcontrol.launch_dependents;" ::: "memory");
}

// ---------------------------------------------------------------------------
// K2: one CTA per segment. Warp-0 prologue folds the chunk-offset reduce
// (former scan_blocks kernel). Hot loop: MLP=16 streaming LDG.128.
// ---------------------------------------------------------------------------
__global__ __launch_bounds__(128)
void seg_mean_kernel(const float* __restrict__ data,
                     const int* __restrict__ sz,
                     float* __restrict__ out, int nb) {
    const int seg = blockIdx.x;
    const int t = threadIdx.x;
    const int w = t >> 5;
    const int l = t & 31;

    const int len = sz[seg];            // independent of scan

    asm volatile("griddepcontrol.wait;" ::: "memory");

    // absolute start = sum of blocktots before my chunk + chunk-local start
    __shared__ int s_start;
    if (w == 0) {
        const int b = seg >> 10;        // my chunk id
        int s = ((l      < b) ? g_blocktot[l]      : 0)
              + ((l + 32 < b) ? g_blocktot[l + 32] : 0);
        #pragma unroll
        for (int d = 16; d > 0; d >>= 1)
            s += __shfl_xor_sync(0xFFFFFFFFu, s, d);
        if (l == 0) s_start = s + g_starts[seg];
    }
    __syncthreads();
    const int start = s_start;

    const float4* __restrict__ base =
        reinterpret_cast<const float4*>(data) + (size_t)start * 32 + l;

    float4 acc = make_float4(0.f, 0.f, 0.f, 0.f);

    if (len == 64) {
        // 16 independent LDG.128 in flight per thread
        float4 v[16];
        #pragma unroll
        for (int i = 0; i < 16; ++i)
            v[i] = __ldcs(&base[(size_t)(w + i * 4) * 32]);
        #pragma unroll
        for (int i = 0; i < 16; ++i) {
            acc.x += v[i].x; acc.y += v[i].y;
            acc.z += v[i].z; acc.w += v[i].w;
        }
    } else {
        int r = w;
        for (; r + 12 < len; r += 16) {
            float4 v0 = __ldcs(&base[(size_t)(r     ) * 32]);
            float4 v1 = __ldcs(&base[(size_t)(r +  4) * 32]);
            float4 v2 = __ldcs(&base[(size_t)(r +  8) * 32]);
            float4 v3 = __ldcs(&base[(size_t)(r + 12) * 32]);
            acc.x += v0.x + v1.x + v2.x + v3.x;
            acc.y += v0.y + v1.y + v2.y + v3.y;
            acc.z += v0.z + v1.z + v2.z + v3.z;
            acc.w += v0.w + v1.w + v2.w + v3.w;
        }
        for (; r < len; r += 4) {
            float4 v = __ldcs(&base[(size_t)r * 32]);
            acc.x += v.x; acc.y += v.y; acc.z += v.z; acc.w += v.w;
        }
    }

    __shared__ float4 sm[4][32];
    sm[w][l] = acc;
    __syncthreads();

    if (w == 0) {
        float4 a = sm[0][l];
        float4 b = sm[1][l];
        float4 c = sm[2][l];
        float4 d = sm[3][l];
        const float inv = (len > 0) ? (1.0f / (float)len) : 0.0f;
        float4 o;
        o.x = (a.x + b.x + c.x + d.x) * inv;
        o.y = (a.y + b.y + c.y + d.y) * inv;
        o.z = (a.z + b.z + c.z + d.z) * inv;
        o.w = (a.w + b.w + c.w + d.w) * inv;
        __stcs(&reinterpret_cast<float4*>(out)[(size_t)seg * 32 + l], o);
    }
}

// ---------------------------------------------------------------------------
// kernel_launch: parallel scan, then PDL-overlapped seg_mean.
// ---------------------------------------------------------------------------
extern "C" void kernel_launch(void* const* d_in, const int* in_sizes, int n_in,
                              void* d_out, int out_size) {
    const float* data = (const float*)d_in[0];
    const int*   sz   = (const int*)d_in[1];
    float*       out  = (float*)d_out;
    const int n_seg = in_sizes[1];
    const int nb    = (n_seg + SCAN_BLK - 1) / SCAN_BLK;

    scan_local_kernel<<<nb, SCAN_BLK>>>(sz, n_seg);

    cudaLaunchConfig_t cfg = {};
    cfg.gridDim  = dim3((unsigned)n_seg, 1, 1);
    cfg.blockDim = dim3(128, 1, 1);
    cfg.dynamicSmemBytes = 0;
    cfg.stream = 0;

    cudaLaunchAttribute attrs[1];
    attrs[0].id = cudaLaunchAttributeProgrammaticStreamSerialization;
    attrs[0].val.programmaticStreamSerializationAllowed = 1;
    cfg.attrs = attrs;
    cfg.numAttrs = 1;

    cudaLaunchKernelEx(&cfg, seg_mean_kernel, data, sz, out, nb);
}